// round 13
// baseline (speedup 1.0000x reference)
#include <cuda_runtime.h>

#define BATCH 16
#define CHN   64
#define HW    65536
#define HW4   (HW / 4)
#define NBLK  64                     // tiles (pool sub-blocks) per batch
#define PGRID 512                    // pool blocks: each does 2 tiles (b and b+8)
#define NNRM  64                     // norm blocks per batch (1 col/thread)
#define NGRID (BATCH * NNRM)         // 1024 norm blocks

// Per-(batch, tile) partials, written fresh each launch (no zeroing):
__device__ float g_part[BATCH][NBLK][8];
// Final per-batch stats: mean0,rstd0,mean1,rstd1,mean2,rstd2,pad,pad
__device__ float g_stats[BATCH][8];
// Per-batch pool-arrival tickets (reset by finalizing block).
__device__ unsigned g_cnt[BATCH] = {0};
// Per-batch stats-ready flags + norm-finish tickets (reset by last norm block).
__device__ volatile unsigned g_done[BATCH];
__device__ unsigned g_nfin[BATCH] = {0};

__device__ __forceinline__ float warp_sum(float v) {
#pragma unroll
    for (int o = 16; o; o >>= 1) v += __shfl_xor_sync(0xffffffffu, v, o);
    return v;
}

__global__ void __launch_bounds__(256) fused_k(
    const float* __restrict__ x,
    const int*   __restrict__ mask,
    float*       __restrict__ out)
{
    const int bid = blockIdx.x;
    const int tid = threadIdx.x;
    const int lane = tid & 31;
    const int wid  = tid >> 5;

    if (bid < PGRID) {
        // ========== POOL block: two tiles, batch b then batch b+8 ==========
        const int b0  = bid >> 6;        // 0..7
        const int blk = bid & 63;
        __shared__ float sh[8][7];

#pragma unroll 1
        for (int half = 0; half < 2; ++half) {
            const int b  = b0 + half * 8;
            const int p4 = blk * 256 + tid;

            const float4* xb = reinterpret_cast<const float4*>(x)
                             + (size_t)b * CHN * HW4 + p4;

            float4 v = __ldcs(&xb[0]);
            float4 vmax = v, vmin = v, vsum = v;
#pragma unroll
            for (int c = 1; c < CHN; ++c) {
                float4 t = __ldcs(&xb[(size_t)c * HW4]);
                vmax.x = fmaxf(vmax.x, t.x); vmax.y = fmaxf(vmax.y, t.y);
                vmax.z = fmaxf(vmax.z, t.z); vmax.w = fmaxf(vmax.w, t.w);
                vmin.x = fminf(vmin.x, t.x); vmin.y = fminf(vmin.y, t.y);
                vmin.z = fminf(vmin.z, t.z); vmin.w = fminf(vmin.w, t.w);
                vsum.x += t.x; vsum.y += t.y; vsum.z += t.z; vsum.w += t.w;
            }
            const float inv = 1.f / (float)CHN;
            float4 vmean = make_float4(vsum.x * inv, vsum.y * inv,
                                       vsum.z * inv, vsum.w * inv);

            float4* ob = reinterpret_cast<float4*>(out) + (size_t)b * 3 * HW4 + p4;
            ob[0]       = vmax;
            ob[HW4]     = vmean;
            ob[2 * HW4] = vmin;

            int4 mk = reinterpret_cast<const int4*>(mask)[(size_t)b * HW4 + p4];
            float m0 = (mk.x == 1) ? 1.f : 0.f;
            float m1 = (mk.y == 1) ? 1.f : 0.f;
            float m2 = (mk.z == 1) ? 1.f : 0.f;
            float m3 = (mk.w == 1) ? 1.f : 0.f;

            float vals[7];
            vals[0] = vmax.x  * m0 + vmax.y  * m1 + vmax.z  * m2 + vmax.w  * m3;
            vals[1] = vmax.x * vmax.x * m0 + vmax.y * vmax.y * m1
                    + vmax.z * vmax.z * m2 + vmax.w * vmax.w * m3;
            vals[2] = vmean.x * m0 + vmean.y * m1 + vmean.z * m2 + vmean.w * m3;
            vals[3] = vmean.x * vmean.x * m0 + vmean.y * vmean.y * m1
                    + vmean.z * vmean.z * m2 + vmean.w * vmean.w * m3;
            vals[4] = vmin.x  * m0 + vmin.y  * m1 + vmin.z  * m2 + vmin.w  * m3;
            vals[5] = vmin.x * vmin.x * m0 + vmin.y * vmin.y * m1
                    + vmin.z * vmin.z * m2 + vmin.w * vmin.w * m3;
            vals[6] = m0 + m1 + m2 + m3;

#pragma unroll
            for (int i = 0; i < 7; ++i) vals[i] = warp_sum(vals[i]);
            if (lane == 0) {
#pragma unroll
                for (int i = 0; i < 7; ++i) sh[wid][i] = vals[i];
            }
            __syncthreads();
            if (wid == 0) {
#pragma unroll
                for (int i = 0; i < 7; ++i) {
                    float t = (lane < 8) ? sh[lane][i] : 0.f;
                    t = warp_sum(t);
                    if (lane == 0) g_part[b][blk][i] = t;
                }

                // ---- last tile of this batch finalizes mean/rstd ----
                unsigned old = 0;
                if (lane == 0) {
                    __threadfence();
                    old = atomicAdd(&g_cnt[b], 1);
                }
                old = __shfl_sync(0xffffffffu, old, 0);
                if (old == NBLK - 1) {
                    __threadfence();
                    // Deterministic fixed-order reduce: lane r sums rows r, r+32.
                    const float4* r0 = reinterpret_cast<const float4*>(&g_part[b][lane][0]);
                    const float4* r1 = reinterpret_cast<const float4*>(&g_part[b][lane + 32][0]);
                    float4 a0 = __ldcg(&r0[0]), a1 = __ldcg(&r0[1]);
                    float4 c0 = __ldcg(&r1[0]), c1 = __ldcg(&r1[1]);
                    float s[7];
                    s[0] = a0.x + c0.x; s[1] = a0.y + c0.y; s[2] = a0.z + c0.z;
                    s[3] = a0.w + c0.w; s[4] = a1.x + c1.x; s[5] = a1.y + c1.y;
                    s[6] = a1.z + c1.z;
#pragma unroll
                    for (int i = 0; i < 7; ++i) s[i] = warp_sum(s[i]);
                    if (lane == 0) {
                        const float cnt = s[6];
#pragma unroll
                        for (int ch = 0; ch < 3; ++ch) {
                            const float sm   = s[2 * ch];
                            const float sq   = s[2 * ch + 1];
                            const float mean = sm / cnt;
                            const float var  = (sq - sm * mean) / (cnt - 1.f);
                            g_stats[b][2 * ch]     = mean;
                            g_stats[b][2 * ch + 1] = rsqrtf(var);
                        }
                        g_cnt[b] = 0;                 // self-reset tickets
                        __threadfence();
                        g_done[b] = 1;                // publish stats-ready
                    }
                }
            }
            __syncthreads();    // protect sh reuse across halves
        }
    } else {
        // ========== NORM block: waits for its batch's stats ==========
        // bids PGRID..PGRID+511  -> batches 0..7  (overlap with pool half 2)
        // bids PGRID+512..+1023  -> batches 8..15 (tail)
        const int nb  = bid - PGRID;
        const int b   = nb >> 6;         // 64 blocks per batch, batch order 0..15
        const int blk = nb & 63;

        // Spin until stats published. Pool blocks never wait -> no deadlock.
        if (tid == 0) {
            while (g_done[b] == 0u) { __nanosleep(128); }
        }
        __syncthreads();
        __threadfence();   // acquire g_stats

        const float4* st4 = reinterpret_cast<const float4*>(&g_stats[b][0]);
        float4 s0 = __ldcg(&st4[0]);
        float4 s1 = __ldcg(&st4[1]);
        const float mean0 = s0.x, rstd0 = s0.y;
        const float mean1 = s0.z, rstd1 = s0.w;
        const float mean2 = s1.x, rstd2 = s1.y;

        const int p4 = blk * 256 + tid;

        const int4* mb = reinterpret_cast<const int4*>(mask) + (size_t)b * HW4;
        float4*     ob = reinterpret_cast<float4*>(out)      + (size_t)b * 3 * HW4;

        int4 mk = mb[p4];
        float4 v0 = ob[p4];
        float4 v1 = ob[HW4 + p4];
        float4 v2 = ob[2 * HW4 + p4];

        v0.x = (mk.x == 1) ? (v0.x - mean0) * rstd0 : 0.f;
        v0.y = (mk.y == 1) ? (v0.y - mean0) * rstd0 : 0.f;
        v0.z = (mk.z == 1) ? (v0.z - mean0) * rstd0 : 0.f;
        v0.w = (mk.w == 1) ? (v0.w - mean0) * rstd0 : 0.f;

        v1.x = (mk.x == 1) ? (v1.x - mean1) * rstd1 : 0.f;
        v1.y = (mk.y == 1) ? (v1.y - mean1) * rstd1 : 0.f;
        v1.z = (mk.z == 1) ? (v1.z - mean1) * rstd1 : 0.f;
        v1.w = (mk.w == 1) ? (v1.w - mean1) * rstd1 : 0.f;

        v2.x = (mk.x == 1) ? (v2.x - mean2) * rstd2 : 0.f;
        v2.y = (mk.y == 1) ? (v2.y - mean2) * rstd2 : 0.f;
        v2.z = (mk.z == 1) ? (v2.z - mean2) * rstd2 : 0.f;
        v2.w = (mk.w == 1) ? (v2.w - mean2) * rstd2 : 0.f;

        ob[p4]           = v0;
        ob[HW4 + p4]     = v1;
        ob[2 * HW4 + p4] = v2;

        // Last norm block of this batch resets the flag for the next launch.
        __syncthreads();
        if (tid == 0) {
            unsigned old = atomicAdd(&g_nfin[b], 1);
            if (old == NNRM - 1) {
                g_nfin[b] = 0;
                g_done[b] = 0;
            }
        }
    }
}

extern "C" void kernel_launch(void* const* d_in, const int* in_sizes, int n_in,
                              void* d_out, int out_size)
{
    const float* x;
    const int*   mask;
    if (in_sizes[0] > in_sizes[1]) {
        x    = (const float*)d_in[0];
        mask = (const int*)d_in[1];
    } else {
        x    = (const float*)d_in[1];
        mask = (const int*)d_in[0];
    }
    float* out = (float*)d_out;

    fused_k<<<PGRID + NGRID, 256>>>(x, mask, out);
}

// round 15
// speedup vs baseline: 1.1411x; 1.1411x over previous
#include <cuda_runtime.h>

#define BATCH 16
#define CHN   64
#define HW    65536
#define HW4   (HW / 4)
#define NBLK  64                     // pool blocks per batch
#define PGRID (BATCH * NBLK)         // 1024 pool blocks (bid 0..1023)
#define NNRM  64                     // norm blocks per batch (1 col/thread)
#define NGRID (BATCH * NNRM)         // 1024 norm blocks

// Per-(batch, block) partials, written fresh each launch (no zeroing):
__device__ float g_part[BATCH][NBLK][8];
// Final per-batch stats: mean0,rstd0,mean1,rstd1,mean2,rstd2,pad,pad
__device__ float g_stats[BATCH][8];
// Per-batch pool-arrival tickets (reset by finalizing block).
__device__ unsigned g_cnt[BATCH] = {0};
// Per-batch stats-ready flags + norm-finish tickets (reset by last norm block).
__device__ volatile unsigned g_done[BATCH];
__device__ unsigned g_nfin[BATCH] = {0};

__device__ __forceinline__ float warp_sum(float v) {
#pragma unroll
    for (int o = 16; o; o >>= 1) v += __shfl_xor_sync(0xffffffffu, v, o);
    return v;
}

__global__ void __launch_bounds__(256) fused_k(
    const float* __restrict__ x,
    const int*   __restrict__ mask,
    float*       __restrict__ out)
{
    const int bid = blockIdx.x;
    const int tid = threadIdx.x;

    if (bid < PGRID) {
        // ================= POOL block (producer): proven streaming body ========
        const int b   = bid >> 6;
        const int blk = bid & 63;
        const int p4  = blk * 256 + tid;

        const float4* xb = reinterpret_cast<const float4*>(x) + (size_t)b * CHN * HW4 + p4;

        float4 v = __ldcs(&xb[0]);
        float4 vmax = v, vmin = v, vsum = v;
#pragma unroll
        for (int c = 1; c < CHN; ++c) {
            float4 t = __ldcs(&xb[(size_t)c * HW4]);
            vmax.x = fmaxf(vmax.x, t.x); vmax.y = fmaxf(vmax.y, t.y);
            vmax.z = fmaxf(vmax.z, t.z); vmax.w = fmaxf(vmax.w, t.w);
            vmin.x = fminf(vmin.x, t.x); vmin.y = fminf(vmin.y, t.y);
            vmin.z = fminf(vmin.z, t.z); vmin.w = fminf(vmin.w, t.w);
            vsum.x += t.x; vsum.y += t.y; vsum.z += t.z; vsum.w += t.w;
        }
        const float inv = 1.f / (float)CHN;
        float4 vmean = make_float4(vsum.x * inv, vsum.y * inv, vsum.z * inv, vsum.w * inv);

        float4* ob = reinterpret_cast<float4*>(out) + (size_t)b * 3 * HW4 + p4;
        ob[0]       = vmax;
        ob[HW4]     = vmean;
        ob[2 * HW4] = vmin;

        int4 mk = reinterpret_cast<const int4*>(mask)[(size_t)b * HW4 + p4];
        float m0 = (mk.x == 1) ? 1.f : 0.f;
        float m1 = (mk.y == 1) ? 1.f : 0.f;
        float m2 = (mk.z == 1) ? 1.f : 0.f;
        float m3 = (mk.w == 1) ? 1.f : 0.f;

        float vals[7];
        vals[0] = vmax.x  * m0 + vmax.y  * m1 + vmax.z  * m2 + vmax.w  * m3;
        vals[1] = vmax.x * vmax.x * m0 + vmax.y * vmax.y * m1
                + vmax.z * vmax.z * m2 + vmax.w * vmax.w * m3;
        vals[2] = vmean.x * m0 + vmean.y * m1 + vmean.z * m2 + vmean.w * m3;
        vals[3] = vmean.x * vmean.x * m0 + vmean.y * vmean.y * m1
                + vmean.z * vmean.z * m2 + vmean.w * vmean.w * m3;
        vals[4] = vmin.x  * m0 + vmin.y  * m1 + vmin.z  * m2 + vmin.w  * m3;
        vals[5] = vmin.x * vmin.x * m0 + vmin.y * vmin.y * m1
                + vmin.z * vmin.z * m2 + vmin.w * vmin.w * m3;
        vals[6] = m0 + m1 + m2 + m3;

        __shared__ float sh[8][7];
        const int lane = tid & 31;
        const int wid  = tid >> 5;

#pragma unroll
        for (int i = 0; i < 7; ++i) vals[i] = warp_sum(vals[i]);
        if (lane == 0) {
#pragma unroll
            for (int i = 0; i < 7; ++i) sh[wid][i] = vals[i];
        }
        __syncthreads();
        if (wid == 0) {
#pragma unroll
            for (int i = 0; i < 7; ++i) {
                float t = (lane < 8) ? sh[lane][i] : 0.f;
                t = warp_sum(t);
                if (lane == 0) g_part[b][blk][i] = t;
            }

            // ---- last pool block of this batch finalizes mean/rstd ----
            unsigned old = 0;
            if (lane == 0) {
                __threadfence();
                old = atomicAdd(&g_cnt[b], 1);
            }
            old = __shfl_sync(0xffffffffu, old, 0);
            if (old == NBLK - 1) {
                __threadfence();
                // Deterministic fixed-order reduce: lane r sums rows r, r+32.
                const float4* r0 = reinterpret_cast<const float4*>(&g_part[b][lane][0]);
                const float4* r1 = reinterpret_cast<const float4*>(&g_part[b][lane + 32][0]);
                float4 a0 = __ldcg(&r0[0]), a1 = __ldcg(&r0[1]);
                float4 b0 = __ldcg(&r1[0]), b1 = __ldcg(&r1[1]);
                float s[7];
                s[0] = a0.x + b0.x; s[1] = a0.y + b0.y; s[2] = a0.z + b0.z;
                s[3] = a0.w + b0.w; s[4] = a1.x + b1.x; s[5] = a1.y + b1.y;
                s[6] = a1.z + b1.z;
#pragma unroll
                for (int i = 0; i < 7; ++i) s[i] = warp_sum(s[i]);
                if (lane == 0) {
                    const float cnt = s[6];
#pragma unroll
                    for (int ch = 0; ch < 3; ++ch) {
                        const float sm   = s[2 * ch];
                        const float sq   = s[2 * ch + 1];
                        const float mean = sm / cnt;
                        const float var  = (sq - sm * mean) / (cnt - 1.f);
                        g_stats[b][2 * ch]     = mean;
                        g_stats[b][2 * ch + 1] = rsqrtf(var);
                    }
                    g_cnt[b] = 0;                 // self-reset tickets
                    __threadfence();
                    g_done[b] = 1;                // publish stats-ready
                }
            }
        }
    } else {
        // ================= NORM block (consumer): waits for its batch ==========
        const int nb  = bid - PGRID;
        const int b   = nb >> 6;          // 64 norm blocks per batch
        const int blk = nb & 63;

        // Spin until stats published. Pool blocks never wait -> no deadlock
        // regardless of residency or dispatch order.
        if (tid == 0) {
            while (g_done[b] == 0u) { __nanosleep(32); }
        }
        __syncthreads();
        __threadfence();   // acquire g_stats

        const float4* st4 = reinterpret_cast<const float4*>(&g_stats[b][0]);
        float4 s0 = __ldcg(&st4[0]);
        float4 s1 = __ldcg(&st4[1]);
        const float mean0 = s0.x, rstd0 = s0.y;
        const float mean1 = s0.z, rstd1 = s0.w;
        const float mean2 = s1.x, rstd2 = s1.y;

        const int p4 = blk * 256 + tid;

        const int4*   mb = reinterpret_cast<const int4*>(mask) + (size_t)b * HW4;
        float4*       ob = reinterpret_cast<float4*>(out)      + (size_t)b * 3 * HW4;

        // Issue all 4 loads before compute (L2-resident; .cg skips L1 fill).
        int4   mk = __ldcg(&mb[p4]);
        float4 v0 = __ldcg(&ob[p4]);
        float4 v1 = __ldcg(&ob[HW4 + p4]);
        float4 v2 = __ldcg(&ob[2 * HW4 + p4]);

        v0.x = (mk.x == 1) ? (v0.x - mean0) * rstd0 : 0.f;
        v0.y = (mk.y == 1) ? (v0.y - mean0) * rstd0 : 0.f;
        v0.z = (mk.z == 1) ? (v0.z - mean0) * rstd0 : 0.f;
        v0.w = (mk.w == 1) ? (v0.w - mean0) * rstd0 : 0.f;

        v1.x = (mk.x == 1) ? (v1.x - mean1) * rstd1 : 0.f;
        v1.y = (mk.y == 1) ? (v1.y - mean1) * rstd1 : 0.f;
        v1.z = (mk.z == 1) ? (v1.z - mean1) * rstd1 : 0.f;
        v1.w = (mk.w == 1) ? (v1.w - mean1) * rstd1 : 0.f;

        v2.x = (mk.x == 1) ? (v2.x - mean2) * rstd2 : 0.f;
        v2.y = (mk.y == 1) ? (v2.y - mean2) * rstd2 : 0.f;
        v2.z = (mk.z == 1) ? (v2.z - mean2) * rstd2 : 0.f;
        v2.w = (mk.w == 1) ? (v2.w - mean2) * rstd2 : 0.f;

        __stcs(&ob[p4],           v0);   // output never re-read: evict-first
        __stcs(&ob[HW4 + p4],     v1);
        __stcs(&ob[2 * HW4 + p4], v2);

        // Last norm block of this batch resets the flag for the next launch.
        __syncthreads();
        if (tid == 0) {
            unsigned old = atomicAdd(&g_nfin[b], 1);
            if (old == NNRM - 1) {
                g_nfin[b] = 0;
                g_done[b] = 0;
            }
        }
    }
}

extern "C" void kernel_launch(void* const* d_in, const int* in_sizes, int n_in,
                              void* d_out, int out_size)
{
    const float* x;
    const int*   mask;
    if (in_sizes[0] > in_sizes[1]) {
        x    = (const float*)d_in[0];
        mask = (const int*)d_in[1];
    } else {
        x    = (const float*)d_in[1];
        mask = (const int*)d_in[0];
    }
    float* out = (float*)d_out;

    fused_k<<<PGRID + NGRID, 256>>>(x, mask, out);
}

// round 16
// speedup vs baseline: 1.1841x; 1.0377x over previous
#include <cuda_runtime.h>

#define BATCH 16
#define CHN   64
#define HW    65536
#define HW4   (HW / 4)
#define NBLK  64                     // pool blocks per batch
#define PGRID (BATCH * NBLK)         // 1024 pool blocks (bid 0..1023)
#define NNRM  32                     // norm blocks per batch (2 cols/thread)
#define NGRID (BATCH * NNRM)         // 512 norm blocks (bid 1024..1535)

// Per-(batch, block) partials, written fresh each launch (no zeroing):
__device__ float g_part[BATCH][NBLK][8];
// Final per-batch stats: mean0,rstd0,mean1,rstd1,mean2,rstd2,pad,pad
__device__ float g_stats[BATCH][8];
// Per-batch pool-arrival tickets (reset by finalizing block).
__device__ unsigned g_cnt[BATCH] = {0};
// Per-batch stats-ready flags + norm-finish tickets (reset by last norm block).
__device__ volatile unsigned g_done[BATCH];
__device__ unsigned g_nfin[BATCH] = {0};

__device__ __forceinline__ float warp_sum(float v) {
#pragma unroll
    for (int o = 16; o; o >>= 1) v += __shfl_xor_sync(0xffffffffu, v, o);
    return v;
}

__global__ void __launch_bounds__(256) fused_k(
    const float* __restrict__ x,
    const int*   __restrict__ mask,
    float*       __restrict__ out)
{
    const int bid = blockIdx.x;
    const int tid = threadIdx.x;

    if (bid < PGRID) {
        // ================= POOL block (producer): streaming body ===============
        const int b   = bid >> 6;
        const int blk = bid & 63;
        const int p4  = blk * 256 + tid;

        const float4* xb = reinterpret_cast<const float4*>(x) + (size_t)b * CHN * HW4 + p4;

        float4 v = __ldcs(&xb[0]);
        float4 vmax = v, vmin = v, vsum = v;
        // unroll 16 (not 64): MLP ~16 still saturates DRAM, but the smaller
        // front-batched LDG window cuts cross-CTA L1tex-queue spread.
#pragma unroll 16
        for (int c = 1; c < CHN; ++c) {
            float4 t = __ldcs(&xb[(size_t)c * HW4]);
            vmax.x = fmaxf(vmax.x, t.x); vmax.y = fmaxf(vmax.y, t.y);
            vmax.z = fmaxf(vmax.z, t.z); vmax.w = fmaxf(vmax.w, t.w);
            vmin.x = fminf(vmin.x, t.x); vmin.y = fminf(vmin.y, t.y);
            vmin.z = fminf(vmin.z, t.z); vmin.w = fminf(vmin.w, t.w);
            vsum.x += t.x; vsum.y += t.y; vsum.z += t.z; vsum.w += t.w;
        }
        const float inv = 1.f / (float)CHN;
        float4 vmean = make_float4(vsum.x * inv, vsum.y * inv, vsum.z * inv, vsum.w * inv);

        float4* ob = reinterpret_cast<float4*>(out) + (size_t)b * 3 * HW4 + p4;
        ob[0]       = vmax;
        ob[HW4]     = vmean;
        ob[2 * HW4] = vmin;

        int4 mk = reinterpret_cast<const int4*>(mask)[(size_t)b * HW4 + p4];
        float m0 = (mk.x == 1) ? 1.f : 0.f;
        float m1 = (mk.y == 1) ? 1.f : 0.f;
        float m2 = (mk.z == 1) ? 1.f : 0.f;
        float m3 = (mk.w == 1) ? 1.f : 0.f;

        float vals[7];
        vals[0] = vmax.x  * m0 + vmax.y  * m1 + vmax.z  * m2 + vmax.w  * m3;
        vals[1] = vmax.x * vmax.x * m0 + vmax.y * vmax.y * m1
                + vmax.z * vmax.z * m2 + vmax.w * vmax.w * m3;
        vals[2] = vmean.x * m0 + vmean.y * m1 + vmean.z * m2 + vmean.w * m3;
        vals[3] = vmean.x * vmean.x * m0 + vmean.y * vmean.y * m1
                + vmean.z * vmean.z * m2 + vmean.w * vmean.w * m3;
        vals[4] = vmin.x  * m0 + vmin.y  * m1 + vmin.z  * m2 + vmin.w  * m3;
        vals[5] = vmin.x * vmin.x * m0 + vmin.y * vmin.y * m1
                + vmin.z * vmin.z * m2 + vmin.w * vmin.w * m3;
        vals[6] = m0 + m1 + m2 + m3;

        __shared__ float sh[8][7];
        const int lane = tid & 31;
        const int wid  = tid >> 5;

#pragma unroll
        for (int i = 0; i < 7; ++i) vals[i] = warp_sum(vals[i]);
        if (lane == 0) {
#pragma unroll
            for (int i = 0; i < 7; ++i) sh[wid][i] = vals[i];
        }
        __syncthreads();
        if (wid == 0) {
#pragma unroll
            for (int i = 0; i < 7; ++i) {
                float t = (lane < 8) ? sh[lane][i] : 0.f;
                t = warp_sum(t);
                if (lane == 0) g_part[b][blk][i] = t;
            }

            // ---- last pool block of this batch finalizes mean/rstd ----
            unsigned old = 0;
            if (lane == 0) {
                __threadfence();
                old = atomicAdd(&g_cnt[b], 1);
            }
            old = __shfl_sync(0xffffffffu, old, 0);
            if (old == NBLK - 1) {
                __threadfence();
                // Deterministic fixed-order reduce: lane r sums rows r, r+32.
                const float4* r0 = reinterpret_cast<const float4*>(&g_part[b][lane][0]);
                const float4* r1 = reinterpret_cast<const float4*>(&g_part[b][lane + 32][0]);
                float4 a0 = __ldcg(&r0[0]), a1 = __ldcg(&r0[1]);
                float4 b0 = __ldcg(&r1[0]), b1 = __ldcg(&r1[1]);
                float s[7];
                s[0] = a0.x + b0.x; s[1] = a0.y + b0.y; s[2] = a0.z + b0.z;
                s[3] = a0.w + b0.w; s[4] = a1.x + b1.x; s[5] = a1.y + b1.y;
                s[6] = a1.z + b1.z;
#pragma unroll
                for (int i = 0; i < 7; ++i) s[i] = warp_sum(s[i]);
                if (lane == 0) {
                    const float cnt = s[6];
#pragma unroll
                    for (int ch = 0; ch < 3; ++ch) {
                        const float sm   = s[2 * ch];
                        const float sq   = s[2 * ch + 1];
                        const float mean = sm / cnt;
                        const float var  = (sq - sm * mean) / (cnt - 1.f);
                        g_stats[b][2 * ch]     = mean;
                        g_stats[b][2 * ch + 1] = rsqrtf(var);
                    }
                    g_cnt[b] = 0;                 // self-reset tickets
                    __threadfence();
                    g_done[b] = 1;                // publish stats-ready
                }
            }
        }
    } else {
        // ================= NORM block (consumer): waits for its batch ==========
        const int nb  = bid - PGRID;
        const int b   = nb >> 5;
        const int blk = nb & 31;

        // Spin until stats published. Pool blocks never wait -> no deadlock.
        if (tid == 0) {
            while (g_done[b] == 0u) { __nanosleep(128); }
        }
        __syncthreads();
        __threadfence();   // acquire g_stats

        const float4* st4 = reinterpret_cast<const float4*>(&g_stats[b][0]);
        float4 s0 = __ldcg(&st4[0]);
        float4 s1 = __ldcg(&st4[1]);
        const float mean0 = s0.x, rstd0 = s0.y;
        const float mean1 = s0.z, rstd1 = s0.w;
        const float mean2 = s1.x, rstd2 = s1.y;

        const int pA = blk * 512 + tid;
        const int pB = pA + 256;

        const int4* mb = reinterpret_cast<const int4*>(mask) + (size_t)b * HW4;
        float4*     ob = reinterpret_cast<float4*>(out)      + (size_t)b * 3 * HW4;

        int4 mkA = mb[pA];
        int4 mkB = mb[pB];
        float4 a0 = ob[pA];             float4 b0 = ob[pB];
        float4 a1 = ob[HW4 + pA];       float4 b1 = ob[HW4 + pB];
        float4 a2 = ob[2 * HW4 + pA];   float4 b2 = ob[2 * HW4 + pB];

        a0.x = (mkA.x == 1) ? (a0.x - mean0) * rstd0 : 0.f;
        a0.y = (mkA.y == 1) ? (a0.y - mean0) * rstd0 : 0.f;
        a0.z = (mkA.z == 1) ? (a0.z - mean0) * rstd0 : 0.f;
        a0.w = (mkA.w == 1) ? (a0.w - mean0) * rstd0 : 0.f;
        a1.x = (mkA.x == 1) ? (a1.x - mean1) * rstd1 : 0.f;
        a1.y = (mkA.y == 1) ? (a1.y - mean1) * rstd1 : 0.f;
        a1.z = (mkA.z == 1) ? (a1.z - mean1) * rstd1 : 0.f;
        a1.w = (mkA.w == 1) ? (a1.w - mean1) * rstd1 : 0.f;
        a2.x = (mkA.x == 1) ? (a2.x - mean2) * rstd2 : 0.f;
        a2.y = (mkA.y == 1) ? (a2.y - mean2) * rstd2 : 0.f;
        a2.z = (mkA.z == 1) ? (a2.z - mean2) * rstd2 : 0.f;
        a2.w = (mkA.w == 1) ? (a2.w - mean2) * rstd2 : 0.f;

        b0.x = (mkB.x == 1) ? (b0.x - mean0) * rstd0 : 0.f;
        b0.y = (mkB.y == 1) ? (b0.y - mean0) * rstd0 : 0.f;
        b0.z = (mkB.z == 1) ? (b0.z - mean0) * rstd0 : 0.f;
        b0.w = (mkB.w == 1) ? (b0.w - mean0) * rstd0 : 0.f;
        b1.x = (mkB.x == 1) ? (b1.x - mean1) * rstd1 : 0.f;
        b1.y = (mkB.y == 1) ? (b1.y - mean1) * rstd1 : 0.f;
        b1.z = (mkB.z == 1) ? (b1.z - mean1) * rstd1 : 0.f;
        b1.w = (mkB.w == 1) ? (b1.w - mean1) * rstd1 : 0.f;
        b2.x = (mkB.x == 1) ? (b2.x - mean2) * rstd2 : 0.f;
        b2.y = (mkB.y == 1) ? (b2.y - mean2) * rstd2 : 0.f;
        b2.z = (mkB.z == 1) ? (b2.z - mean2) * rstd2 : 0.f;
        b2.w = (mkB.w == 1) ? (b2.w - mean2) * rstd2 : 0.f;

        ob[pA]           = a0;   ob[pB]           = b0;
        ob[HW4 + pA]     = a1;   ob[HW4 + pB]     = b1;
        ob[2 * HW4 + pA] = a2;   ob[2 * HW4 + pB] = b2;

        // Last norm block of this batch resets the flag for the next launch.
        __syncthreads();
        if (tid == 0) {
            unsigned old = atomicAdd(&g_nfin[b], 1);
            if (old == NNRM - 1) {
                g_nfin[b] = 0;
                g_done[b] = 0;
            }
        }
    }
}

extern "C" void kernel_launch(void* const* d_in, const int* in_sizes, int n_in,
                              void* d_out, int out_size)
{
    const float* x;
    const int*   mask;
    if (in_sizes[0] > in_sizes[1]) {
        x    = (const float*)d_in[0];
        mask = (const int*)d_in[1];
    } else {
        x    = (const float*)d_in[1];
        mask = (const int*)d_in[0];
    }
    float* out = (float*)d_out;

    fused_k<<<PGRID + NGRID, 256>>>(x, mask, out);
}